// round 7
// baseline (speedup 1.0000x reference)
#include <cuda_runtime.h>
#include <cstddef>

#define Hd 10
#define Td 20
#define M1 5

// ---- activations ----
__device__ __forceinline__ float tanh_fast(float x) {
    float r; asm("tanh.approx.f32 %0, %1;" : "=f"(r) : "f"(x)); return r;
}
__device__ __forceinline__ float sig_fast(float x) {
    return fmaf(tanh_fast(0.5f * x), 0.5f, 0.5f);   // 1 MUFU
}
__device__ __forceinline__ float sig_acc(float x) {  // accurate, for final score
    return __fdividef(1.0f, 1.0f + __expf(-x));
}

__global__ void __launch_bounds__(128, 5)
lstm_disc_kernel(const float* __restrict__ values,
                 const float* __restrict__ masks,
                 const float* __restrict__ W_ih,   // (40,1)
                 const float* __restrict__ W_hh,   // (40,10) row-major
                 const float* __restrict__ b_ih,   // (40)
                 const float* __restrict__ b_hh,   // (40)
                 const float* __restrict__ W1,     // (5,10)
                 const float* __restrict__ b1,     // (5)
                 const float* __restrict__ W2,     // (1,5)
                 const float* __restrict__ b2,     // (1)
                 float* __restrict__ out,          // scores (B,T) then masks (B,T)
                 int B)
{
    // Gate-pair packed layout. For lane-pair p (lanes 2p,2p+1), h-index k:
    // sWg[p][k] = { Wi[2p],Wi[2p+1], Wf[2p],Wf[2p+1], Wg[2p],Wg[2p+1], Wo[2p],Wo[2p+1] }
    __shared__ __align__(16) float sWg[5][Hd][8];
    // sBX[p][0..7] = bias pairs (gate order i,f,g,o), sBX[p][8..15] = W_ih pairs
    __shared__ __align__(16) float sBX[5][16];
    // MLP: W1 rows padded to 12 floats (3 float4), cols 10..11 zero
    __shared__ __align__(16) float sW1r[M1][12];
    __shared__ float sB1[M1];
    __shared__ float sW2[M1];
    __shared__ float sB2;

    const int tid = threadIdx.x;
    for (int i = tid; i < 5 * Hd * 8; i += blockDim.x) {
        int p = i / 80, r = i % 80, k = r / 8, g = r % 8;
        int j = (g >> 1) * 10 + 2 * p + (g & 1);   // gate row index in [0,40)
        sWg[p][k][g] = W_hh[j * Hd + k];
    }
    if (tid < 80) {
        int p = tid / 16, r = tid % 16;
        int g = (r < 8) ? r : r - 8;
        int j = (g >> 1) * 10 + 2 * p + (g & 1);
        sBX[p][r] = (r < 8) ? (b_ih[j] + b_hh[j]) : W_ih[j];
    }
    if (tid < M1 * 12) {
        int j = tid / 12, k = tid % 12;
        sW1r[j][k] = (k < Hd) ? W1[j * Hd + k] : 0.0f;
    }
    if (tid < M1) { sB1[tid] = b1[tid]; sW2[tid] = W2[tid]; }
    if (tid == 0) sB2 = b2[0];
    __syncthreads();

    const int b = blockIdx.x * blockDim.x + tid;
    if (b >= B) return;

    const float* __restrict__ vrow = values + (size_t)b * Td;
    float* __restrict__ srow = out + (size_t)b * Td;

    float h[12], c[Hd];
#pragma unroll
    for (int k = 0; k < Hd; k++) { h[k] = 0.f; c[k] = 0.f; }
    h[10] = 0.f; h[11] = 0.f;                  // padding lanes for float4 MLP

#pragma unroll 1
    for (int t = 0; t < Td; t++) {
        // ---- MLP scoring head on pre-update h (float4 LDS, scalar FMA) ----
        float acc = sB2;
#pragma unroll
        for (int j = 0; j < M1; j++) {
            const float4* __restrict__ wr = (const float4*)sW1r[j];
            float z = sB1[j];
#pragma unroll
            for (int q = 0; q < 3; q++) {
                const float4 w = wr[q];
                z = fmaf(h[4 * q],     w.x, z);
                z = fmaf(h[4 * q + 1], w.y, z);
                z = fmaf(h[4 * q + 2], w.z, z);
                z = fmaf(h[4 * q + 3], w.w, z);
            }
            z = fmaxf(z, 0.2f * z);            // leaky_relu(0.2)
            acc = fmaf(sW2[j], z, acc);
        }
        srow[t] = sig_acc(acc);

        // ---- LSTM gates, p-block at a time (8 scalar accumulators live) ----
        const float x = vrow[t];
        float hn[Hd];
#pragma unroll
        for (int p = 0; p < 5; p++) {
            const float4* __restrict__ bx = (const float4*)sBX[p];
            const float4 b0 = bx[0], b1v = bx[1], w0 = bx[2], w1v = bx[3];
            float aI0 = fmaf(x, w0.x,  b0.x),  aI1 = fmaf(x, w0.y,  b0.y);
            float aF0 = fmaf(x, w0.z,  b0.z),  aF1 = fmaf(x, w0.w,  b0.w);
            float aG0 = fmaf(x, w1v.x, b1v.x), aG1 = fmaf(x, w1v.y, b1v.y);
            float aO0 = fmaf(x, w1v.z, b1v.z), aO1 = fmaf(x, w1v.w, b1v.w);

            const float4* __restrict__ wg = (const float4*)&sWg[p][0][0];
#pragma unroll
            for (int k = 0; k < Hd; k++) {
                const float4 wIF = wg[2 * k];      // i0,i1,f0,f1
                const float4 wGO = wg[2 * k + 1];  // g0,g1,o0,o1
                const float hk = h[k];
                aI0 = fmaf(hk, wIF.x, aI0);  aI1 = fmaf(hk, wIF.y, aI1);
                aF0 = fmaf(hk, wIF.z, aF0);  aF1 = fmaf(hk, wIF.w, aF1);
                aG0 = fmaf(hk, wGO.x, aG0);  aG1 = fmaf(hk, wGO.y, aG1);
                aO0 = fmaf(hk, wGO.z, aO0);  aO1 = fmaf(hk, wGO.w, aO1);
            }

            const float cn0 = fmaf(sig_fast(aF0), c[2 * p],     sig_fast(aI0) * tanh_fast(aG0));
            const float cn1 = fmaf(sig_fast(aF1), c[2 * p + 1], sig_fast(aI1) * tanh_fast(aG1));
            c[2 * p] = cn0; c[2 * p + 1] = cn1;
            hn[2 * p]     = sig_fast(aO0) * tanh_fast(cn0);
            hn[2 * p + 1] = sig_fast(aO1) * tanh_fast(cn1);
        }
#pragma unroll
        for (int k = 0; k < Hd; k++) h[k] = hn[k];
    }

    // ---- masks passthrough: one row = 20 floats = 5 float4 ----
    const float4* __restrict__ m0 = (const float4*)(masks + (size_t)b * Td);
    float4* __restrict__ mo = (float4*)(out + (size_t)B * Td + (size_t)b * Td);
#pragma unroll
    for (int q = 0; q < Td / 4; q++) mo[q] = m0[q];
}

extern "C" void kernel_launch(void* const* d_in, const int* in_sizes, int n_in,
                              void* d_out, int out_size)
{
    const float* values = (const float*)d_in[0];
    const float* masks  = (const float*)d_in[1];
    const float* W_ih   = (const float*)d_in[2];
    const float* W_hh   = (const float*)d_in[3];
    const float* b_ih   = (const float*)d_in[4];
    const float* b_hh   = (const float*)d_in[5];
    const float* W1     = (const float*)d_in[6];
    const float* b1     = (const float*)d_in[7];
    const float* W2     = (const float*)d_in[8];
    const float* b2     = (const float*)d_in[9];

    const int BT = in_sizes[0];          // B*T
    const int B  = BT / Td;
    float* out = (float*)d_out;

    lstm_disc_kernel<<<(B + 127) / 128, 128>>>(
        values, masks, W_ih, W_hh, b_ih, b_hh, W1, b1, W2, b2, out, B);
}

// round 8
// speedup vs baseline: 8.8389x; 8.8389x over previous
#include <cuda_runtime.h>
#include <cstddef>

#define Hd 10
#define Td 20
#define M1 5

// ---- activations ----
__device__ __forceinline__ float tanh_fast(float x) {
    float r; asm("tanh.approx.f32 %0, %1;" : "=f"(r) : "f"(x)); return r;
}
__device__ __forceinline__ float sig_fast(float x) {
    return fmaf(tanh_fast(0.5f * x), 0.5f, 0.5f);   // 1 MUFU
}
__device__ __forceinline__ float sig_acc(float x) {  // accurate, for final score
    return __fdividef(1.0f, 1.0f + __expf(-x));
}

__global__ void __launch_bounds__(256, 2)
lstm_disc_kernel(const float* __restrict__ values,
                 const float* __restrict__ masks,
                 const float* __restrict__ W_ih,   // (40,1)
                 const float* __restrict__ W_hh,   // (40,10) row-major
                 const float* __restrict__ b_ih,   // (40)
                 const float* __restrict__ b_hh,   // (40)
                 const float* __restrict__ W1,     // (5,10)
                 const float* __restrict__ b1,     // (5)
                 const float* __restrict__ W2,     // (1,5)
                 const float* __restrict__ b2,     // (1)
                 float* __restrict__ out,          // scores (B,T) then masks (B,T)
                 int B)
{
    // Lane-major gate weights: sW[u][k] = float4{ Wi[u][k], Wf[u][k], Wg[u][k], Wo[u][k] }
    // Gate row for gate g, lane u is W_hh[g*10+u].
    __shared__ __align__(16) float sW[Hd][Hd][4];   // 1600 B
    __shared__ __align__(16) float sBias[Hd][4];    // b_ih+b_hh per lane, gate order i,f,g,o
    __shared__ __align__(16) float sWx[Hd][4];      // W_ih per lane, gate order
    __shared__ __align__(16) float sW1r[M1][12];    // W1 rows padded to 12 (3x float4)
    __shared__ float sB1[M1];
    __shared__ float sW2[M1];
    __shared__ float sB2;

    const int tid = threadIdx.x;
    for (int i = tid; i < Hd * Hd * 4; i += blockDim.x) {
        int u = i / 40, r = i % 40, k = r / 4, g = r % 4;
        sW[u][k][g] = W_hh[(g * 10 + u) * Hd + k];
    }
    if (tid < Hd * 4) {
        int u = tid / 4, g = tid % 4;
        int j = g * 10 + u;
        sBias[u][g] = b_ih[j] + b_hh[j];
        sWx[u][g]   = W_ih[j];
    }
    if (tid < M1 * 12) {
        int j = tid / 12, k = tid % 12;
        sW1r[j][k] = (k < Hd) ? W1[j * Hd + k] : 0.0f;
    }
    if (tid < M1) { sB1[tid] = b1[tid]; sW2[tid] = W2[tid]; }
    if (tid == 0) sB2 = b2[0];
    __syncthreads();

    const int gtid = blockIdx.x * blockDim.x + tid;
    const int e = gtid >> 1;             // element index
    const int q = gtid & 1;              // which half of the element (lanes 5q..5q+4)
    const int ub = 5 * q;

    const int nthreads = gridDim.x * blockDim.x;

    if (e < B) {
        const float* __restrict__ vrow = values + (size_t)e * Td;
        float* __restrict__ srow = out + (size_t)e * Td;

        float h[Hd + 2], c[5];
#pragma unroll
        for (int k = 0; k < Hd + 2; k++) h[k] = 0.f;
#pragma unroll
        for (int k = 0; k < 5; k++) c[k] = 0.f;

#pragma unroll 1
        for (int t = 0; t < Td; t++) {
            // ---- MLP scoring head on pre-update h, split by row parity ----
            // q==0 does rows 0,2,4 (and carries sB2); q==1 does rows 1,3.
            float part = (q == 0) ? sB2 : 0.0f;
#pragma unroll
            for (int jj = 0; jj < 3; jj++) {
                const int j = 2 * jj + q;
                if (j < M1) {
                    const float4* __restrict__ wr = (const float4*)sW1r[j];
                    float z = sB1[j];
#pragma unroll
                    for (int p = 0; p < 3; p++) {
                        const float4 w = wr[p];
                        z = fmaf(h[4 * p],     w.x, z);
                        z = fmaf(h[4 * p + 1], w.y, z);
                        z = fmaf(h[4 * p + 2], w.z, z);
                        z = fmaf(h[4 * p + 3], w.w, z);
                    }
                    z = fmaxf(z, 0.2f * z);          // leaky_relu(0.2)
                    part = fmaf(sW2[j], z, part);
                }
            }
            const float opart = __shfl_xor_sync(0xffffffffu, part, 1);
            if (q == 0) srow[t] = sig_acc(part + opart);

            // ---- LSTM gates for owned lanes ub..ub+4, one lane at a time ----
            const float x = vrow[t];
            float hn[5];
#pragma unroll
            for (int l = 0; l < 5; l++) {
                const int u = ub + l;
                const float4 bi = *(const float4*)sBias[u];
                const float4 wx = *(const float4*)sWx[u];
                float aI = fmaf(x, wx.x, bi.x);
                float aF = fmaf(x, wx.y, bi.y);
                float aG = fmaf(x, wx.z, bi.z);
                float aO = fmaf(x, wx.w, bi.w);
                const float4* __restrict__ wrow = (const float4*)&sW[u][0][0];
#pragma unroll
                for (int k = 0; k < Hd; k++) {
                    const float4 w = wrow[k];
                    const float hk = h[k];
                    aI = fmaf(hk, w.x, aI);
                    aF = fmaf(hk, w.y, aF);
                    aG = fmaf(hk, w.z, aG);
                    aO = fmaf(hk, w.w, aO);
                }
                const float cn = fmaf(sig_fast(aF), c[l], sig_fast(aI) * tanh_fast(aG));
                c[l] = cn;
                hn[l] = sig_fast(aO) * tanh_fast(cn);
            }

            // ---- exchange h halves with partner thread ----
#pragma unroll
            for (int i = 0; i < 5; i++) {
                const float v = __shfl_xor_sync(0xffffffffu, hn[i], 1);
                h[i]     = (q == 0) ? hn[i] : v;
                h[5 + i] = (q == 0) ? v : hn[i];
            }
        }
    }

    // ---- masks passthrough: coalesced grid-stride float4 copy ----
    {
        const float4* __restrict__ mi = (const float4*)masks;
        float4* __restrict__ mo = (float4*)(out + (size_t)B * Td);
        const int n4 = (B * Td) / 4;
#pragma unroll 1
        for (int i = gtid; i < n4; i += nthreads) mo[i] = mi[i];
    }
}

extern "C" void kernel_launch(void* const* d_in, const int* in_sizes, int n_in,
                              void* d_out, int out_size)
{
    const float* values = (const float*)d_in[0];
    const float* masks  = (const float*)d_in[1];
    const float* W_ih   = (const float*)d_in[2];
    const float* W_hh   = (const float*)d_in[3];
    const float* b_ih   = (const float*)d_in[4];
    const float* b_hh   = (const float*)d_in[5];
    const float* W1     = (const float*)d_in[6];
    const float* b1     = (const float*)d_in[7];
    const float* W2     = (const float*)d_in[8];
    const float* b2     = (const float*)d_in[9];

    const int BT = in_sizes[0];          // B*T
    const int B  = BT / Td;
    float* out = (float*)d_out;

    const int nthreads = 2 * B;          // 2 threads per element
    lstm_disc_kernel<<<(nthreads + 255) / 256, 256>>>(
        values, masks, W_ih, W_hh, b_ih, b_hh, W1, b1, W2, b2, out, B);
}

// round 9
// speedup vs baseline: 11.3948x; 1.2892x over previous
#include <cuda_runtime.h>
#include <cstddef>

#define Hd 10
#define Td 20
#define M1 5

// ---- activations ----
__device__ __forceinline__ float tanh_fast(float x) {
    float r; asm("tanh.approx.f32 %0, %1;" : "=f"(r) : "f"(x)); return r;
}
__device__ __forceinline__ float sig_fast(float x) {
    return fmaf(tanh_fast(0.5f * x), 0.5f, 0.5f);   // 1 MUFU
}
__device__ __forceinline__ float sig_acc(float x) {  // accurate, for final score
    return __fdividef(1.0f, 1.0f + __expf(-x));
}

__global__ void __launch_bounds__(256, 2)
lstm_disc_kernel(const float* __restrict__ values,
                 const float* __restrict__ masks,
                 const float* __restrict__ W_ih,   // (40,1)
                 const float* __restrict__ W_hh,   // (40,10) row-major
                 const float* __restrict__ b_ih,   // (40)
                 const float* __restrict__ b_hh,   // (40)
                 const float* __restrict__ W1,     // (5,10)
                 const float* __restrict__ b1,     // (5)
                 const float* __restrict__ W2,     // (1,5)
                 const float* __restrict__ b2,     // (1)
                 float* __restrict__ out,          // scores (B,T) then masks (B,T)
                 int B)
{
    // Lane-major gate weights: sW[u][k] = float4{ Wi[u][k], Wf[u][k], Wg[u][k], Wo[u][k] }
    __shared__ __align__(16) float sW[Hd][Hd][4];   // 1600 B
    __shared__ __align__(16) float sBias[Hd][4];    // b_ih+b_hh per lane, gate order i,f,g,o
    __shared__ __align__(16) float sWx[Hd][4];      // W_ih per lane, gate order
    __shared__ __align__(16) float sW1r[M1][12];    // W1 rows padded to 12 (3x float4)
    __shared__ float sB1[M1];
    __shared__ float sW2[M1];
    __shared__ float sB2;

    const int tid = threadIdx.x;
    for (int i = tid; i < Hd * Hd * 4; i += blockDim.x) {
        int u = i / 40, r = i % 40, k = r / 4, g = r % 4;
        sW[u][k][g] = W_hh[(g * 10 + u) * Hd + k];
    }
    if (tid < Hd * 4) {
        int u = tid / 4, g = tid % 4;
        int j = g * 10 + u;
        sBias[u][g] = b_ih[j] + b_hh[j];
        sWx[u][g]   = W_ih[j];
    }
    if (tid < M1 * 12) {
        int j = tid / 12, k = tid % 12;
        sW1r[j][k] = (k < Hd) ? W1[j * Hd + k] : 0.0f;
    }
    if (tid < M1) { sB1[tid] = b1[tid]; sW2[tid] = W2[tid]; }
    if (tid == 0) sB2 = b2[0];
    __syncthreads();

    const int gtid = blockIdx.x * blockDim.x + tid;
    const int pr = gtid >> 1;            // pair index -> elements 2pr, 2pr+1
    const int q  = gtid & 1;             // which lane-half this thread owns
    const int ub = 5 * q;
    const int nthreads = gridDim.x * blockDim.x;

    const int e0 = 2 * pr, e1 = 2 * pr + 1;
    if (e1 < B) {
        const float* __restrict__ vr0 = values + (size_t)e0 * Td;
        const float* __restrict__ vr1 = values + (size_t)e1 * Td;
        float* __restrict__ sr0 = out + (size_t)e0 * Td;
        float* __restrict__ sr1 = out + (size_t)e1 * Td;

        float h0[Hd + 2], h1[Hd + 2], c0[5], c1[5];
#pragma unroll
        for (int k = 0; k < Hd + 2; k++) { h0[k] = 0.f; h1[k] = 0.f; }
#pragma unroll
        for (int k = 0; k < 5; k++) { c0[k] = 0.f; c1[k] = 0.f; }

#pragma unroll 1
        for (int t = 0; t < Td; t++) {
            // ---- MLP scoring head (pre-update h), rows split by parity,
            //      weight rows loaded once and applied to BOTH elements ----
            float p0 = (q == 0) ? sB2 : 0.0f;
            float p1 = p0;
#pragma unroll
            for (int jj = 0; jj < 3; jj++) {
                const int j = 2 * jj + q;
                if (j < M1) {
                    const float4* __restrict__ wr = (const float4*)sW1r[j];
                    float z0 = sB1[j], z1 = z0;
#pragma unroll
                    for (int p4 = 0; p4 < 3; p4++) {
                        const float4 w = wr[p4];
                        z0 = fmaf(h0[4 * p4],     w.x, z0);
                        z0 = fmaf(h0[4 * p4 + 1], w.y, z0);
                        z0 = fmaf(h0[4 * p4 + 2], w.z, z0);
                        z0 = fmaf(h0[4 * p4 + 3], w.w, z0);
                        z1 = fmaf(h1[4 * p4],     w.x, z1);
                        z1 = fmaf(h1[4 * p4 + 1], w.y, z1);
                        z1 = fmaf(h1[4 * p4 + 2], w.z, z1);
                        z1 = fmaf(h1[4 * p4 + 3], w.w, z1);
                    }
                    z0 = fmaxf(z0, 0.2f * z0);       // leaky_relu(0.2)
                    z1 = fmaxf(z1, 0.2f * z1);
                    const float w2j = sW2[j];
                    p0 = fmaf(w2j, z0, p0);
                    p1 = fmaf(w2j, z1, p1);
                }
            }
            const float o0 = __shfl_xor_sync(0xffffffffu, p0, 1);
            const float o1 = __shfl_xor_sync(0xffffffffu, p1, 1);
            if (q == 0) sr0[t] = sig_acc(p0 + o0);
            else        sr1[t] = sig_acc(p1 + o1);

            // ---- LSTM gates: each weight float4 feeds 8 FMAs (4 gates x 2 elems) ----
            const float x0 = vr0[t];
            const float x1 = vr1[t];
            float hn0[5], hn1[5];
#pragma unroll
            for (int l = 0; l < 5; l++) {
                const int u = ub + l;
                const float4 bi = *(const float4*)sBias[u];
                const float4 wx = *(const float4*)sWx[u];
                float aI0 = fmaf(x0, wx.x, bi.x), aF0 = fmaf(x0, wx.y, bi.y);
                float aG0 = fmaf(x0, wx.z, bi.z), aO0 = fmaf(x0, wx.w, bi.w);
                float aI1 = fmaf(x1, wx.x, bi.x), aF1 = fmaf(x1, wx.y, bi.y);
                float aG1 = fmaf(x1, wx.z, bi.z), aO1 = fmaf(x1, wx.w, bi.w);

                const float4* __restrict__ wrow = (const float4*)&sW[u][0][0];
#pragma unroll
                for (int k = 0; k < Hd; k++) {
                    const float4 w = wrow[k];
                    const float a = h0[k], b = h1[k];
                    aI0 = fmaf(a, w.x, aI0);  aF0 = fmaf(a, w.y, aF0);
                    aG0 = fmaf(a, w.z, aG0);  aO0 = fmaf(a, w.w, aO0);
                    aI1 = fmaf(b, w.x, aI1);  aF1 = fmaf(b, w.y, aF1);
                    aG1 = fmaf(b, w.z, aG1);  aO1 = fmaf(b, w.w, aO1);
                }
                const float cn0 = fmaf(sig_fast(aF0), c0[l], sig_fast(aI0) * tanh_fast(aG0));
                const float cn1 = fmaf(sig_fast(aF1), c1[l], sig_fast(aI1) * tanh_fast(aG1));
                c0[l] = cn0; c1[l] = cn1;
                hn0[l] = sig_fast(aO0) * tanh_fast(cn0);
                hn1[l] = sig_fast(aO1) * tanh_fast(cn1);
            }

            // ---- exchange h halves with partner thread (both elements) ----
#pragma unroll
            for (int i = 0; i < 5; i++) {
                const float v0 = __shfl_xor_sync(0xffffffffu, hn0[i], 1);
                const float v1 = __shfl_xor_sync(0xffffffffu, hn1[i], 1);
                h0[i]     = (q == 0) ? hn0[i] : v0;
                h0[5 + i] = (q == 0) ? v0 : hn0[i];
                h1[i]     = (q == 0) ? hn1[i] : v1;
                h1[5 + i] = (q == 0) ? v1 : hn1[i];
            }
        }
    }

    // ---- masks passthrough: coalesced grid-stride float4 copy ----
    {
        const float4* __restrict__ mi = (const float4*)masks;
        float4* __restrict__ mo = (float4*)(out + (size_t)B * Td);
        const int n4 = (B * Td) / 4;
#pragma unroll 1
        for (int i = gtid; i < n4; i += nthreads) mo[i] = mi[i];
    }
}

extern "C" void kernel_launch(void* const* d_in, const int* in_sizes, int n_in,
                              void* d_out, int out_size)
{
    const float* values = (const float*)d_in[0];
    const float* masks  = (const float*)d_in[1];
    const float* W_ih   = (const float*)d_in[2];
    const float* W_hh   = (const float*)d_in[3];
    const float* b_ih   = (const float*)d_in[4];
    const float* b_hh   = (const float*)d_in[5];
    const float* W1     = (const float*)d_in[6];
    const float* b1     = (const float*)d_in[7];
    const float* W2     = (const float*)d_in[8];
    const float* b2     = (const float*)d_in[9];

    const int BT = in_sizes[0];          // B*T
    const int B  = BT / Td;
    float* out = (float*)d_out;

    const int nthreads = B;              // 2 threads per 2 elements
    lstm_disc_kernel<<<(nthreads + 255) / 256, 256>>>(
        values, masks, W_ih, W_hh, b_ih, b_hh, W1, b1, W2, b2, out, B);
}